// round 8
// baseline (speedup 1.0000x reference)
#include <cuda_runtime.h>
#include <cuda_bf16.h>
#include <stdint.h>
#include <math.h>

#define INF_ 1e10f

__device__ float g_dots [8388608];
__device__ float g_WqT  [1048576];
__device__ float g_WkT  [1048576];
__device__ float g_c1   [1024];
__device__ float g_c2   [1024];
__device__ float g_c3   [1];
__device__ float g_steps[64];
__device__ float g_at   [8192];
__device__ float g_bs   [8192];
__device__ float g_gates[8192];
__device__ __nv_bfloat16 g_keyB  [8388608];
__device__ __nv_bfloat16 g_queryB[8388608];
__device__ __nv_bfloat16 g_qmB   [8388608];
__device__ __nv_bfloat16 g_MtB   [1048576];
__device__ __nv_bfloat16 g_WqTB  [1048576];
__device__ __nv_bfloat16 g_WkTB  [1048576];

// ---------- helpers ----------
__device__ __forceinline__ uint32_t pkbf(float a, float b) {
    __nv_bfloat162 t = __halves2bfloat162(__float2bfloat16(a), __float2bfloat16(b));
    return *reinterpret_cast<uint32_t*>(&t);
}
__device__ __forceinline__ float wsum(float v) {
    #pragma unroll
    for (int o = 16; o; o >>= 1) v += __shfl_xor_sync(0xffffffffu, v, o);
    return v;
}
__device__ __forceinline__ float wmax(float v) {
    #pragma unroll
    for (int o = 16; o; o >>= 1) v = fmaxf(v, __shfl_xor_sync(0xffffffffu, v, o));
    return v;
}
__device__ float bsum(float v, float* sb) {
    int lane = threadIdx.x & 31, w = threadIdx.x >> 5, nw = (blockDim.x + 31) >> 5;
    v = wsum(v);
    if (lane == 0) sb[w] = v;
    __syncthreads();
    v = (threadIdx.x < nw) ? sb[threadIdx.x] : 0.f;
    if (w == 0) v = wsum(v);
    if (threadIdx.x == 0) sb[0] = v;
    __syncthreads();
    v = sb[0];
    __syncthreads();
    return v;
}
__device__ float bmax(float v, float* sb) {
    int lane = threadIdx.x & 31, w = threadIdx.x >> 5, nw = (blockDim.x + 31) >> 5;
    v = wmax(v);
    if (lane == 0) sb[w] = v;
    __syncthreads();
    v = (threadIdx.x < nw) ? sb[threadIdx.x] : -INFINITY;
    if (w == 0) v = wmax(v);
    if (threadIdx.x == 0) sb[0] = v;
    __syncthreads();
    v = sb[0];
    __syncthreads();
    return v;
}

// ---------- small kernels ----------
__global__ void k_steps(const float* __restrict__ ms, const float* __restrict__ mt,
                        int B, int S, int T) {
    int b = blockIdx.x;
    __shared__ float sb[32];
    float s = 0.f;
    for (int i = threadIdx.x; i < S; i += blockDim.x) s += ms[(size_t)b * S + i];
    s = bsum(s, sb);
    float t = 0.f;
    for (int i = threadIdx.x; i < T; i += blockDim.x) t += mt[(size_t)b * T + i];
    t = bsum(t, sb);
    if (threadIdx.x == 0) g_steps[b] = s / t;
}

__global__ void k_c3(const float* __restrict__ bq, const float* __restrict__ bk, int D) {
    __shared__ float sb[32];
    float s = 0.f;
    for (int i = threadIdx.x; i < D; i += blockDim.x) s += bq[i] * bk[i];
    s = bsum(s, sb);
    if (threadIdx.x == 0) g_c3[0] = s;
}

__global__ void k_transp(const float* __restrict__ in, float* __restrict__ outp,
                         __nv_bfloat16* __restrict__ outb, int D) {
    __shared__ float t[32][33];
    int x0 = blockIdx.x * 32, y0 = blockIdx.y * 32;
    int tx = threadIdx.x, ty = threadIdx.y;
    #pragma unroll
    for (int j = 0; j < 32; j += 8)
        t[ty + j][tx] = in[(size_t)(y0 + ty + j) * D + x0 + tx];
    __syncthreads();
    #pragma unroll
    for (int j = 0; j < 32; j += 8) {
        float v = t[tx][ty + j];
        size_t idx = (size_t)(x0 + ty + j) * D + y0 + tx;
        outp[idx] = v;
        outb[idx] = __float2bfloat16(v);
    }
}

__global__ void k_cvecR(const float* __restrict__ bq, const float* __restrict__ bk, int D) {
    int e = blockIdx.x;
    __shared__ float sb[32];
    const float4* r1 = (const float4*)(g_WqT + (size_t)e * D);
    const float4* r2 = (const float4*)(g_WkT + (size_t)e * D);
    float s1 = 0.f, s2 = 0.f;
    for (int i = threadIdx.x; i < D / 4; i += blockDim.x) {
        float4 a = r1[i], c = *(const float4*)(bk + i * 4);
        s1 += a.x * c.x + a.y * c.y + a.z * c.z + a.w * c.w;
        float4 b2 = r2[i], d2 = *(const float4*)(bq + i * 4);
        s2 += b2.x * d2.x + b2.y * d2.y + b2.z * d2.z + b2.w * d2.w;
    }
    s1 = bsum(s1, sb);
    s2 = bsum(s2, sb);
    if (threadIdx.x == 0) { g_c1[e] = s1; g_c2[e] = s2; }
}

__global__ void k_bskey(const float* __restrict__ key, int D) {
    int r = blockIdx.x;
    __shared__ float sb[32];
    float s = 0.f;
    const float4* kr = (const float4*)(key + (size_t)r * D);
    uint2* ob = (uint2*)(g_keyB + (size_t)r * D);
    for (int i = threadIdx.x; i < D / 4; i += blockDim.x) {
        float4 kv = kr[i], cv = *(const float4*)(g_c2 + i * 4);
        s += kv.x * cv.x + kv.y * cv.y + kv.z * cv.z + kv.w * cv.w;
        uint2 p;
        p.x = pkbf(kv.x, kv.y);
        p.y = pkbf(kv.z, kv.w);
        ob[i] = p;
    }
    s = bsum(s, sb);
    if (threadIdx.x == 0) g_bs[r] = s;
}

// ---------- windowed query = l_att @ key, fused gates/at ----------
#define QT 16
__global__ __launch_bounds__(256) void k_query(const float* __restrict__ mask_src,
                                               const float* __restrict__ key,
                                               const float* __restrict__ wg,
                                               const float* __restrict__ bg,
                                               int B, int T, int S, int D) {
    __shared__ float wk[QT][64];
    __shared__ float s_c[QT], s_m[QT], s_inv[QT];
    __shared__ int s_s0[QT], s_s1[QT], sh_lo, sh_hi;
    __shared__ float red1[QT], red2[QT];
    int b = blockIdx.y, t0 = blockIdx.x * QT, tid = threadIdx.x;
    int lane = tid & 31;
    float step = g_steps[b];
    if (tid < QT) {
        red1[tid] = 0.f; red2[tid] = 0.f;
        int t = t0 + tid;
        if (t < T) {
            float c = step * (float)t;
            int ci = (int)lrintf(c);
            ci = min(max(ci, 0), S - 1);
            int a0 = max(0, ci - 16), a1 = min(S - 1, ci + 16);
            float mx = -INFINITY;
            for (int s = a0; s <= a1; s++) {
                float d = (float)s - c;
                mx = fmaxf(mx, -(d * d) / 0.3f - INF_ * (1.0f - mask_src[(size_t)b * S + s]));
            }
            float sum = 0.f;
            for (int s = a0; s <= a1; s++) {
                float d = (float)s - c;
                sum += __expf(-(d * d) / 0.3f - INF_ * (1.0f - mask_src[(size_t)b * S + s]) - mx);
            }
            s_c[tid] = c; s_m[tid] = mx; s_inv[tid] = 1.0f / sum;
            s_s0[tid] = a0; s_s1[tid] = a1;
        } else {
            s_c[tid] = 0.f; s_m[tid] = 0.f; s_inv[tid] = 0.f;
            s_s0[tid] = 1; s_s1[tid] = 0;
        }
    }
    __syncthreads();
    if (tid == 0) {
        int lo = s_s0[0], hi = s_s1[0];
        for (int i = 1; i < QT; i++)
            if (s_s1[i] >= s_s0[i]) { lo = min(lo, s_s0[i]); hi = max(hi, s_s1[i]); }
        sh_lo = lo; sh_hi = hi;
    }
    __syncthreads();
    int lo = sh_lo, hi = sh_hi;
    float4 acc[QT];
    #pragma unroll
    for (int r = 0; r < QT; r++) acc[r] = make_float4(0.f, 0.f, 0.f, 0.f);
    for (int c0 = lo; c0 <= hi; c0 += 64) {
        int cnt = min(64, hi - c0 + 1);
        __syncthreads();
        for (int i = tid; i < QT * 64; i += 256) {
            int tr = i >> 6, j = i & 63, s = c0 + j;
            float w = 0.f;
            if (j < cnt && s >= s_s0[tr] && s <= s_s1[tr]) {
                float d = (float)s - s_c[tr];
                w = __expf(-(d * d) / 0.3f - INF_ * (1.0f - mask_src[(size_t)b * S + s]) - s_m[tr]) * s_inv[tr];
            }
            wk[tr][j] = w;
        }
        __syncthreads();
        for (int j = 0; j < cnt; j++) {
            float4 kv = *(const float4*)(key + ((size_t)b * S + c0 + j) * D + tid * 4);
            #pragma unroll
            for (int r = 0; r < QT; r++) {
                float w = wk[r][j];
                acc[r].x = fmaf(w, kv.x, acc[r].x);
                acc[r].y = fmaf(w, kv.y, acc[r].y);
                acc[r].z = fmaf(w, kv.z, acc[r].z);
                acc[r].w = fmaf(w, kv.w, acc[r].w);
            }
        }
        __syncthreads();
    }
    float4 wgv = *(const float4*)(wg + tid * 4);
    float4 c1v = *(const float4*)(g_c1 + tid * 4);
    #pragma unroll
    for (int r = 0; r < QT; r++) {
        int t = t0 + r;
        if (t < T) {
            size_t base = ((size_t)b * T + t) * D + tid * 4;
            uint2 p;
            p.x = pkbf(acc[r].x, acc[r].y);
            p.y = pkbf(acc[r].z, acc[r].w);
            *(uint2*)(g_queryB + base) = p;
        }
        float p1 = acc[r].x * wgv.x + acc[r].y * wgv.y + acc[r].z * wgv.z + acc[r].w * wgv.w;
        float p2 = acc[r].x * c1v.x + acc[r].y * c1v.y + acc[r].z * c1v.z + acc[r].w * c1v.w;
        p1 = wsum(p1);
        p2 = wsum(p2);
        if (lane == 0) { atomicAdd(&red1[r], p1); atomicAdd(&red2[r], p2); }
    }
    __syncthreads();
    if (tid < QT) {
        int t = t0 + tid;
        if (t < T) {
            g_gates[(size_t)b * T + t] = 1.0f / (1.0f + __expf(-(red1[tid] + bg[0])));
            g_at[(size_t)b * T + t] = red2[tid];
        }
    }
}

// ---------- mma wrappers ----------
__device__ __forceinline__ void mma_bf16(float* c, const uint32_t* a, const uint32_t* b) {
    asm volatile("mma.sync.aligned.m16n8k16.row.col.f32.bf16.bf16.f32 "
                 "{%0,%1,%2,%3},{%4,%5,%6,%7},{%8,%9},{%0,%1,%2,%3};"
                 : "+f"(c[0]), "+f"(c[1]), "+f"(c[2]), "+f"(c[3])
                 : "r"(a[0]), "r"(a[1]), "r"(a[2]), "r"(a[3]), "r"(b[0]), "r"(b[1]));
}
__device__ __forceinline__ void cpa16(uint32_t saddr, const void* g) {
    asm volatile("cp.async.cg.shared.global [%0], [%1], 16;" :: "r"(saddr), "l"(g));
}
__device__ __forceinline__ void ldsm4(uint32_t* r, uint32_t addr) {
    asm volatile("ldmatrix.sync.aligned.m8n8.x4.shared.b16 {%0,%1,%2,%3}, [%4];"
                 : "=r"(r[0]), "=r"(r[1]), "=r"(r[2]), "=r"(r[3]) : "r"(addr));
}

// ---------- bf16 NT GEMM (ldmatrix, 4-stage cp.async): C[m,n] = sum_k A[m,k]*B[n,k] ----------
#define BQ 40
#define STG 4
#define SPITCH (128 * BQ)
#define GEMM_SMEM (STG * SPITCH * 2 * 2)   // bytes: 4 stages * (A+B) * 128*40 bf16
__global__ __launch_bounds__(256) void k_bfgemm(
    const __nv_bfloat16* __restrict__ A, const __nv_bfloat16* __restrict__ B, void* __restrict__ Cout,
    int K, int lda, int ldb, int ldc,
    long long Abat, long long Bbat, long long Cbat, int bf16out,
    const float* __restrict__ rowadd, int rowbat,
    const float* __restrict__ coladd, int colbat,
    const float* __restrict__ scalaradd)
{
    extern __shared__ __align__(16) __nv_bfloat16 dsm[];
    __nv_bfloat16* Asb = dsm;
    __nv_bfloat16* Bsb = dsm + STG * SPITCH;
    int tid = threadIdx.x, lane = tid & 31, wid = tid >> 5;
    int bz = blockIdx.z;
    A += Abat * bz; B += Bbat * bz;
    int m0 = blockIdx.y * 128, n0 = blockIdx.x * 128;
    int wm = (wid & 1) * 64, wn = (wid >> 1) * 32;
    float acc[4][4][4] = {};
    int lrow = tid >> 1, lcol = (tid & 1) * 16;
    const __nv_bfloat16* agp = A + (size_t)(m0 + lrow) * lda + lcol;
    const __nv_bfloat16* bgp = B + (size_t)(n0 + lrow) * ldb + lcol;
    int nk = K >> 5;
    int soff = lrow * BQ + lcol;
    #define LTB(kt, st) do { int _k = (kt) * 32; int _o = (st) * SPITCH + soff; \
        cpa16((uint32_t)__cvta_generic_to_shared(Asb + _o), agp + _k); \
        cpa16((uint32_t)__cvta_generic_to_shared(Asb + _o + 8), agp + _k + 8); \
        cpa16((uint32_t)__cvta_generic_to_shared(Bsb + _o), bgp + _k); \
        cpa16((uint32_t)__cvta_generic_to_shared(Bsb + _o + 8), bgp + _k + 8); \
    } while (0)

    #pragma unroll
    for (int i = 0; i < STG - 1; i++) {
        if (i < nk) LTB(i, i);
        asm volatile("cp.async.commit_group;");
    }
    int arow = (lane & 15), aoffb = (lane >> 4) * 8;
    int gq = lane >> 3;
    int brow = (gq >> 1) * 8 + (lane & 7), boffb = (gq & 1) * 8;
    for (int kt = 0; kt < nk; kt++) {
        int st = kt & (STG - 1);
        asm volatile("cp.async.wait_group %0;" :: "n"(STG - 2));
        __syncthreads();
        const __nv_bfloat16* Ast = Asb + st * SPITCH;
        const __nv_bfloat16* Bst = Bsb + st * SPITCH;
        #pragma unroll
        for (int kk = 0; kk < 32; kk += 16) {
            uint32_t ar[4][4], br[4][2];
            #pragma unroll
            for (int mi = 0; mi < 4; mi++)
                ldsm4(ar[mi], (uint32_t)__cvta_generic_to_shared(
                    Ast + (wm + mi * 16 + arow) * BQ + kk + aoffb));
            #pragma unroll
            for (int nj = 0; nj < 2; nj++) {
                uint32_t t4[4];
                ldsm4(t4, (uint32_t)__cvta_generic_to_shared(
                    Bst + (wn + nj * 16 + brow) * BQ + kk + boffb));
                br[nj * 2][0] = t4[0];
                br[nj * 2][1] = t4[1];
                br[nj * 2 + 1][0] = t4[2];
                br[nj * 2 + 1][1] = t4[3];
            }
            #pragma unroll
            for (int mi = 0; mi < 4; mi++)
                #pragma unroll
                for (int ni = 0; ni < 4; ni++)
                    mma_bf16(acc[mi][ni], ar[mi], br[ni]);
        }
        __syncthreads();
        if (kt + STG - 1 < nk) LTB(kt + STG - 1, (kt + STG - 1) & (STG - 1));
        asm volatile("cp.async.commit_group;");
    }
    float sc = scalaradd ? scalaradd[0] : 0.f;
    #pragma unroll
    for (int mi = 0; mi < 4; mi++) {
        int r0 = m0 + wm + mi * 16 + (lane >> 2);
        float ra0 = sc + (rowadd ? rowadd[(size_t)rowbat * bz + r0] : 0.f);
        float ra1 = sc + (rowadd ? rowadd[(size_t)rowbat * bz + r0 + 8] : 0.f);
        #pragma unroll
        for (int ni = 0; ni < 4; ni++) {
            int c0 = n0 + wn + ni * 8 + (lane & 3) * 2;
            float cb0 = coladd ? coladd[(size_t)colbat * bz + c0] : 0.f;
            float cb1 = coladd ? coladd[(size_t)colbat * bz + c0 + 1] : 0.f;
            float v00 = acc[mi][ni][0] + ra0 + cb0, v01 = acc[mi][ni][1] + ra0 + cb1;
            float v10 = acc[mi][ni][2] + ra1 + cb0, v11 = acc[mi][ni][3] + ra1 + cb1;
            if (bf16out) {
                __nv_bfloat16* Cb = (__nv_bfloat16*)Cout + Cbat * bz;
                *(uint32_t*)(Cb + (size_t)r0 * ldc + c0) = pkbf(v00, v01);
                *(uint32_t*)(Cb + (size_t)(r0 + 8) * ldc + c0) = pkbf(v10, v11);
            } else {
                float* Cf = (float*)Cout + Cbat * bz;
                *(float2*)(Cf + (size_t)r0 * ldc + c0) = make_float2(v00, v01);
                *(float2*)(Cf + (size_t)(r0 + 8) * ldc + c0) = make_float2(v10, v11);
            }
        }
    }
}

// ---------- final ----------
__global__ void k_final(const float* __restrict__ mask_src, float* __restrict__ out,
                        const float* __restrict__ dots, int B, int T, int S, float invscale) {
    int bt = blockIdx.x;
    int b = bt / T, t = bt - b * T;
    extern __shared__ float sm[];
    float* sp = sm;
    float* sl = sm + S;
    __shared__ float sred[32];
    float c = g_steps[b] * (float)t;
    float lmax = -INFINITY, qmax = -INFINITY;
    for (int s = threadIdx.x; s < S; s += blockDim.x) {
        float msk = 1.0f - mask_src[(size_t)b * S + s];
        float d = (float)s - c;
        float lg = -(d * d) / 0.3f - INF_ * msk;
        sl[s] = lg;
        lmax = fmaxf(lmax, lg);
        float x = (dots[(size_t)bt * S + s] - msk * INF_) * invscale;
        sp[s] = x;
        qmax = fmaxf(qmax, x);
    }
    lmax = bmax(lmax, sred);
    qmax = bmax(qmax, sred);
    float lsum = 0.f, qsum = 0.f;
    for (int s = threadIdx.x; s < S; s += blockDim.x) {
        float el = __expf(sl[s] - lmax);
        sl[s] = el;
        lsum += el;
        float eq = __expf(sp[s] - qmax);
        sp[s] = eq;
        qsum += eq;
    }
    lsum = bsum(lsum, sred);
    qsum = bsum(qsum, sred);
    float linv = 1.0f / lsum, qinv = 1.0f / qsum;
    float g = g_gates[bt];
    for (int s = threadIdx.x; s < S; s += blockDim.x)
        out[(size_t)bt * S + s] = (1.0f - g) * (sp[s] * qinv) + g * (sl[s] * linv);
}

// ---------- launch ----------
extern "C" void kernel_launch(void* const* d_in, const int* in_sizes, int n_in,
                              void* d_out, int out_size) {
    const float* key      = (const float*)d_in[0];
    const float* mask_src = (const float*)d_in[1];
    const float* mask_trg = (const float*)d_in[2];
    const float* Wq       = (const float*)d_in[3];
    const float* bq       = (const float*)d_in[4];
    const float* Wk       = (const float*)d_in[5];
    const float* bk       = (const float*)d_in[6];
    const float* wg       = (const float*)d_in[7];
    const float* bg       = (const float*)d_in[8];
    float* out = (float*)d_out;

    int D  = in_sizes[4];
    int BT = in_sizes[2];
    int S  = out_size / BT;
    int B  = in_sizes[1] / S;
    int T  = BT / B;

    float *p_WqT, *p_WkT, *p_c3, *p_at, *p_bs, *p_dots;
    __nv_bfloat16 *p_keyB, *p_queryB, *p_qmB, *p_MtB, *p_WqTB, *p_WkTB;
    cudaGetSymbolAddress((void**)&p_WqT,   g_WqT);
    cudaGetSymbolAddress((void**)&p_WkT,   g_WkT);
    cudaGetSymbolAddress((void**)&p_c3,    g_c3);
    cudaGetSymbolAddress((void**)&p_at,    g_at);
    cudaGetSymbolAddress((void**)&p_bs,    g_bs);
    cudaGetSymbolAddress((void**)&p_dots,  g_dots);
    cudaGetSymbolAddress((void**)&p_keyB,  g_keyB);
    cudaGetSymbolAddress((void**)&p_queryB, g_queryB);
    cudaGetSymbolAddress((void**)&p_qmB,   g_qmB);
    cudaGetSymbolAddress((void**)&p_MtB,   g_MtB);
    cudaGetSymbolAddress((void**)&p_WqTB,  g_WqTB);
    cudaGetSymbolAddress((void**)&p_WkTB,  g_WkTB);

    cudaFuncSetAttribute(k_bfgemm, cudaFuncAttributeMaxDynamicSharedMemorySize, GEMM_SMEM);

    k_steps<<<B, 256>>>(mask_src, mask_trg, B, S, T);
    k_c3<<<1, 256>>>(bq, bk, D);
    {
        dim3 tb(32, 8);
        dim3 g(D / 32, D / 32);
        k_transp<<<g, tb>>>(Wq, p_WqT, p_WqTB, D);
        k_transp<<<g, tb>>>(Wk, p_WkT, p_WkTB, D);
    }
    k_cvecR<<<D, 128>>>(bq, bk, D);
    k_bskey<<<B * S, 128>>>(key, D);
    {
        dim3 g((T + QT - 1) / QT, B);
        k_query<<<g, 256>>>(mask_src, key, wg, bg, B, T, S, D);
    }

    // MtB[n,k] = sum_d WkTB[n,d]*WqTB[k,d]
    {
        dim3 g(D / 128, D / 128, 1);
        k_bfgemm<<<g, 256, GEMM_SMEM>>>(p_WkTB, p_WqTB, p_MtB, D, D, D, D,
                                        0, 0, 0, 1, nullptr, 0, nullptr, 0, nullptr);
    }
    // qmB[m,n] = sum_k queryB[m,k]*MtB[n,k]
    {
        dim3 g(D / 128, BT / 128, 1);
        k_bfgemm<<<g, 256, GEMM_SMEM>>>(p_queryB, p_MtB, p_qmB, D, D, D, D,
                                        0, 0, 0, 1, nullptr, 0, nullptr, 0, nullptr);
    }
    // dots[b][t,s] = sum_k qmB[b][t,k]*keyB[b][s,k] + at + bs + c3
    {
        dim3 g(S / 128, T / 128, B);
        k_bfgemm<<<g, 256, GEMM_SMEM>>>(p_qmB, p_keyB, p_dots, D, D, D, S,
                                        (long long)T * D, (long long)S * D, (long long)T * S, 0,
                                        p_at, T, p_bs, S, p_c3);
    }

    k_final<<<B * T, 256, 2 * S * (int)sizeof(float)>>>(mask_src, out, p_dots, B, T, S,
                                                        1.0f / sqrtf((float)D));
}

// round 9
// speedup vs baseline: 1.0604x; 1.0604x over previous
#include <cuda_runtime.h>
#include <cuda_bf16.h>
#include <stdint.h>
#include <math.h>

#define INF_ 1e10f

__device__ float g_dots [8388608];
__device__ float g_WqT  [1048576];
__device__ float g_WkT  [1048576];
__device__ float g_c1   [1024];
__device__ float g_c2   [1024];
__device__ float g_c3   [1];
__device__ float g_steps[64];
__device__ float g_at   [8192];
__device__ float g_bs   [8192];
__device__ float g_gates[8192];
__device__ __nv_bfloat16 g_keyB  [8388608];
__device__ __nv_bfloat16 g_queryB[8388608];
__device__ __nv_bfloat16 g_qmB   [8388608];
__device__ __nv_bfloat16 g_MtB   [1048576];
__device__ __nv_bfloat16 g_WqTB  [1048576];
__device__ __nv_bfloat16 g_WkTB  [1048576];

// ---------- helpers ----------
__device__ __forceinline__ uint32_t pkbf(float a, float b) {
    __nv_bfloat162 t = __halves2bfloat162(__float2bfloat16(a), __float2bfloat16(b));
    return *reinterpret_cast<uint32_t*>(&t);
}
__device__ __forceinline__ float wsum(float v) {
    #pragma unroll
    for (int o = 16; o; o >>= 1) v += __shfl_xor_sync(0xffffffffu, v, o);
    return v;
}
__device__ __forceinline__ float wmax(float v) {
    #pragma unroll
    for (int o = 16; o; o >>= 1) v = fmaxf(v, __shfl_xor_sync(0xffffffffu, v, o));
    return v;
}
__device__ float bsum(float v, float* sb) {
    int lane = threadIdx.x & 31, w = threadIdx.x >> 5, nw = (blockDim.x + 31) >> 5;
    v = wsum(v);
    if (lane == 0) sb[w] = v;
    __syncthreads();
    v = (threadIdx.x < nw) ? sb[threadIdx.x] : 0.f;
    if (w == 0) v = wsum(v);
    if (threadIdx.x == 0) sb[0] = v;
    __syncthreads();
    v = sb[0];
    __syncthreads();
    return v;
}
__device__ float bmax(float v, float* sb) {
    int lane = threadIdx.x & 31, w = threadIdx.x >> 5, nw = (blockDim.x + 31) >> 5;
    v = wmax(v);
    if (lane == 0) sb[w] = v;
    __syncthreads();
    v = (threadIdx.x < nw) ? sb[threadIdx.x] : -INFINITY;
    if (w == 0) v = wmax(v);
    if (threadIdx.x == 0) sb[0] = v;
    __syncthreads();
    v = sb[0];
    __syncthreads();
    return v;
}

// ---------- small kernels ----------
__global__ void k_steps(const float* __restrict__ ms, const float* __restrict__ mt,
                        int B, int S, int T) {
    int b = blockIdx.x;
    __shared__ float sb[32];
    float s = 0.f;
    for (int i = threadIdx.x; i < S; i += blockDim.x) s += ms[(size_t)b * S + i];
    s = bsum(s, sb);
    float t = 0.f;
    for (int i = threadIdx.x; i < T; i += blockDim.x) t += mt[(size_t)b * T + i];
    t = bsum(t, sb);
    if (threadIdx.x == 0) g_steps[b] = s / t;
}

// transpose both Wq (z=0) and Wk (z=1): fp32 + bf16 outputs
__global__ void k_transp2(const float* __restrict__ Wq, const float* __restrict__ Wk, int D) {
    __shared__ float t[32][33];
    const float* in = blockIdx.z ? Wk : Wq;
    float* outp = blockIdx.z ? g_WkT : g_WqT;
    __nv_bfloat16* outb = blockIdx.z ? g_WkTB : g_WqTB;
    int x0 = blockIdx.x * 32, y0 = blockIdx.y * 32;
    int tx = threadIdx.x, ty = threadIdx.y;
    #pragma unroll
    for (int j = 0; j < 32; j += 8)
        t[ty + j][tx] = in[(size_t)(y0 + ty + j) * D + x0 + tx];
    __syncthreads();
    #pragma unroll
    for (int j = 0; j < 32; j += 8) {
        float v = t[tx][ty + j];
        size_t idx = (size_t)(x0 + ty + j) * D + y0 + tx;
        outp[idx] = v;
        outb[idx] = __float2bfloat16(v);
    }
}

// c1[e] = dot(WqT[e,:], bk); c2[e] = dot(WkT[e,:], bq); block 0 also c3 = bq.bk
__global__ void k_cvecR(const float* __restrict__ bq, const float* __restrict__ bk, int D) {
    int e = blockIdx.x;
    __shared__ float sb[32];
    const float4* r1 = (const float4*)(g_WqT + (size_t)e * D);
    const float4* r2 = (const float4*)(g_WkT + (size_t)e * D);
    float s1 = 0.f, s2 = 0.f, s3 = 0.f;
    for (int i = threadIdx.x; i < D / 4; i += blockDim.x) {
        float4 a = r1[i], c = *(const float4*)(bk + i * 4);
        s1 += a.x * c.x + a.y * c.y + a.z * c.z + a.w * c.w;
        float4 b2 = r2[i], d2 = *(const float4*)(bq + i * 4);
        s2 += b2.x * d2.x + b2.y * d2.y + b2.z * d2.z + b2.w * d2.w;
        if (e == 0) s3 += d2.x * c.x + d2.y * c.y + d2.z * c.z + d2.w * c.w;
    }
    s1 = bsum(s1, sb);
    s2 = bsum(s2, sb);
    if (e == 0) {
        s3 = bsum(s3, sb);
        if (threadIdx.x == 0) g_c3[0] = s3;
    }
    if (threadIdx.x == 0) { g_c1[e] = s1; g_c2[e] = s2; }
}

__global__ void k_bskey(const float* __restrict__ key, int D) {
    int r = blockIdx.x;
    __shared__ float sb[32];
    float s = 0.f;
    const float4* kr = (const float4*)(key + (size_t)r * D);
    uint2* ob = (uint2*)(g_keyB + (size_t)r * D);
    for (int i = threadIdx.x; i < D / 4; i += blockDim.x) {
        float4 kv = kr[i], cv = *(const float4*)(g_c2 + i * 4);
        s += kv.x * cv.x + kv.y * cv.y + kv.z * cv.z + kv.w * cv.w;
        uint2 p;
        p.x = pkbf(kv.x, kv.y);
        p.y = pkbf(kv.z, kv.w);
        ob[i] = p;
    }
    s = bsum(s, sb);
    if (threadIdx.x == 0) g_bs[r] = s;
}

// ---------- windowed query = l_att @ key, fused gates/at ----------
#define QT 16
__global__ __launch_bounds__(256) void k_query(const float* __restrict__ mask_src,
                                               const float* __restrict__ key,
                                               const float* __restrict__ wg,
                                               const float* __restrict__ bg,
                                               int B, int T, int S, int D) {
    __shared__ float wk[QT][64];
    __shared__ float s_c[QT], s_m[QT], s_inv[QT];
    __shared__ int s_s0[QT], s_s1[QT], sh_lo, sh_hi;
    __shared__ float red1[QT], red2[QT];
    int b = blockIdx.y, t0 = blockIdx.x * QT, tid = threadIdx.x;
    int lane = tid & 31;
    float step = g_steps[b];
    if (tid < QT) {
        red1[tid] = 0.f; red2[tid] = 0.f;
        int t = t0 + tid;
        if (t < T) {
            float c = step * (float)t;
            int ci = (int)lrintf(c);
            ci = min(max(ci, 0), S - 1);
            int a0 = max(0, ci - 16), a1 = min(S - 1, ci + 16);
            float mx = -INFINITY;
            for (int s = a0; s <= a1; s++) {
                float d = (float)s - c;
                mx = fmaxf(mx, -(d * d) / 0.3f - INF_ * (1.0f - mask_src[(size_t)b * S + s]));
            }
            float sum = 0.f;
            for (int s = a0; s <= a1; s++) {
                float d = (float)s - c;
                sum += __expf(-(d * d) / 0.3f - INF_ * (1.0f - mask_src[(size_t)b * S + s]) - mx);
            }
            s_c[tid] = c; s_m[tid] = mx; s_inv[tid] = 1.0f / sum;
            s_s0[tid] = a0; s_s1[tid] = a1;
        } else {
            s_c[tid] = 0.f; s_m[tid] = 0.f; s_inv[tid] = 0.f;
            s_s0[tid] = 1; s_s1[tid] = 0;
        }
    }
    __syncthreads();
    if (tid == 0) {
        int lo = s_s0[0], hi = s_s1[0];
        for (int i = 1; i < QT; i++)
            if (s_s1[i] >= s_s0[i]) { lo = min(lo, s_s0[i]); hi = max(hi, s_s1[i]); }
        sh_lo = lo; sh_hi = hi;
    }
    __syncthreads();
    int lo = sh_lo, hi = sh_hi;
    float4 acc[QT];
    #pragma unroll
    for (int r = 0; r < QT; r++) acc[r] = make_float4(0.f, 0.f, 0.f, 0.f);
    for (int c0 = lo; c0 <= hi; c0 += 64) {
        int cnt = min(64, hi - c0 + 1);
        __syncthreads();
        for (int i = tid; i < QT * 64; i += 256) {
            int tr = i >> 6, j = i & 63, s = c0 + j;
            float w = 0.f;
            if (j < cnt && s >= s_s0[tr] && s <= s_s1[tr]) {
                float d = (float)s - s_c[tr];
                w = __expf(-(d * d) / 0.3f - INF_ * (1.0f - mask_src[(size_t)b * S + s]) - s_m[tr]) * s_inv[tr];
            }
            wk[tr][j] = w;
        }
        __syncthreads();
        for (int j = 0; j < cnt; j++) {
            float4 kv = *(const float4*)(key + ((size_t)b * S + c0 + j) * D + tid * 4);
            #pragma unroll
            for (int r = 0; r < QT; r++) {
                float w = wk[r][j];
                acc[r].x = fmaf(w, kv.x, acc[r].x);
                acc[r].y = fmaf(w, kv.y, acc[r].y);
                acc[r].z = fmaf(w, kv.z, acc[r].z);
                acc[r].w = fmaf(w, kv.w, acc[r].w);
            }
        }
        __syncthreads();
    }
    float4 wgv = *(const float4*)(wg + tid * 4);
    float4 c1v = *(const float4*)(g_c1 + tid * 4);
    #pragma unroll
    for (int r = 0; r < QT; r++) {
        int t = t0 + r;
        if (t < T) {
            size_t base = ((size_t)b * T + t) * D + tid * 4;
            uint2 p;
            p.x = pkbf(acc[r].x, acc[r].y);
            p.y = pkbf(acc[r].z, acc[r].w);
            *(uint2*)(g_queryB + base) = p;
        }
        float p1 = acc[r].x * wgv.x + acc[r].y * wgv.y + acc[r].z * wgv.z + acc[r].w * wgv.w;
        float p2 = acc[r].x * c1v.x + acc[r].y * c1v.y + acc[r].z * c1v.z + acc[r].w * c1v.w;
        p1 = wsum(p1);
        p2 = wsum(p2);
        if (lane == 0) { atomicAdd(&red1[r], p1); atomicAdd(&red2[r], p2); }
    }
    __syncthreads();
    if (tid < QT) {
        int t = t0 + tid;
        if (t < T) {
            g_gates[(size_t)b * T + t] = 1.0f / (1.0f + __expf(-(red1[tid] + bg[0])));
            g_at[(size_t)b * T + t] = red2[tid];
        }
    }
}

// ---------- mma wrappers ----------
__device__ __forceinline__ void mma_bf16(float* c, const uint32_t* a, const uint32_t* b) {
    asm volatile("mma.sync.aligned.m16n8k16.row.col.f32.bf16.bf16.f32 "
                 "{%0,%1,%2,%3},{%4,%5,%6,%7},{%8,%9},{%0,%1,%2,%3};"
                 : "+f"(c[0]), "+f"(c[1]), "+f"(c[2]), "+f"(c[3])
                 : "r"(a[0]), "r"(a[1]), "r"(a[2]), "r"(a[3]), "r"(b[0]), "r"(b[1]));
}
__device__ __forceinline__ void cpa16(uint32_t saddr, const void* g) {
    asm volatile("cp.async.cg.shared.global [%0], [%1], 16;" :: "r"(saddr), "l"(g));
}
__device__ __forceinline__ void ldsm4(uint32_t* r, uint32_t addr) {
    asm volatile("ldmatrix.sync.aligned.m8n8.x4.shared.b16 {%0,%1,%2,%3}, [%4];"
                 : "=r"(r[0]), "=r"(r[1]), "=r"(r[2]), "=r"(r[3]) : "r"(addr));
}

// ---------- bf16 NT GEMM (ldmatrix, 4-stage, 2 CTAs/SM): C[m,n] = sum_k A[m,k]*B[n,k] ----------
#define BQ 40
#define STG 4
#define SPITCH (128 * BQ)
#define GEMM_SMEM (STG * SPITCH * 2 * 2)
__global__ __launch_bounds__(256, 2) void k_bfgemm(
    const __nv_bfloat16* __restrict__ A, const __nv_bfloat16* __restrict__ B, void* __restrict__ Cout,
    int K, int lda, int ldb, int ldc,
    long long Abat, long long Bbat, long long Cbat, int bf16out,
    const float* __restrict__ rowadd, int rowbat,
    const float* __restrict__ coladd, int colbat,
    const float* __restrict__ scalaradd)
{
    extern __shared__ __align__(16) __nv_bfloat16 dsm[];
    __nv_bfloat16* Asb = dsm;
    __nv_bfloat16* Bsb = dsm + STG * SPITCH;
    int tid = threadIdx.x, lane = tid & 31, wid = tid >> 5;
    int bz = blockIdx.z;
    A += Abat * bz; B += Bbat * bz;
    int m0 = blockIdx.y * 128, n0 = blockIdx.x * 128;
    int wm = (wid & 1) * 64, wn = (wid >> 1) * 32;
    float acc[4][4][4] = {};
    int lrow = tid >> 1, lcol = (tid & 1) * 16;
    const __nv_bfloat16* agp = A + (size_t)(m0 + lrow) * lda + lcol;
    const __nv_bfloat16* bgp = B + (size_t)(n0 + lrow) * ldb + lcol;
    int nk = K >> 5;
    int soff = lrow * BQ + lcol;
    #define LTB(kt, st) do { int _k = (kt) * 32; int _o = (st) * SPITCH + soff; \
        cpa16((uint32_t)__cvta_generic_to_shared(Asb + _o), agp + _k); \
        cpa16((uint32_t)__cvta_generic_to_shared(Asb + _o + 8), agp + _k + 8); \
        cpa16((uint32_t)__cvta_generic_to_shared(Bsb + _o), bgp + _k); \
        cpa16((uint32_t)__cvta_generic_to_shared(Bsb + _o + 8), bgp + _k + 8); \
    } while (0)

    #pragma unroll
    for (int i = 0; i < STG - 1; i++) {
        if (i < nk) LTB(i, i);
        asm volatile("cp.async.commit_group;");
    }
    int arow = (lane & 15), aoffb = (lane >> 4) * 8;
    int gq = lane >> 3;
    int brow = (gq >> 1) * 8 + (lane & 7), boffb = (gq & 1) * 8;
    for (int kt = 0; kt < nk; kt++) {
        int st = kt & (STG - 1);
        asm volatile("cp.async.wait_group %0;" :: "n"(STG - 2));
        __syncthreads();
        const __nv_bfloat16* Ast = Asb + st * SPITCH;
        const __nv_bfloat16* Bst = Bsb + st * SPITCH;
        #pragma unroll
        for (int kk = 0; kk < 32; kk += 16) {
            uint32_t ar[4][4], br[4][2];
            #pragma unroll
            for (int mi = 0; mi < 4; mi++)
                ldsm4(ar[mi], (uint32_t)__cvta_generic_to_shared(
                    Ast + (wm + mi * 16 + arow) * BQ + kk + aoffb));
            #pragma unroll
            for (int nj = 0; nj < 2; nj++) {
                uint32_t t4[4];
                ldsm4(t4, (uint32_t)__cvta_generic_to_shared(
                    Bst + (wn + nj * 16 + brow) * BQ + kk + boffb));
                br[nj * 2][0] = t4[0];
                br[nj * 2][1] = t4[1];
                br[nj * 2 + 1][0] = t4[2];
                br[nj * 2 + 1][1] = t4[3];
            }
            #pragma unroll
            for (int mi = 0; mi < 4; mi++)
                #pragma unroll
                for (int ni = 0; ni < 4; ni++)
                    mma_bf16(acc[mi][ni], ar[mi], br[ni]);
        }
        __syncthreads();
        if (kt + STG - 1 < nk) LTB(kt + STG - 1, (kt + STG - 1) & (STG - 1));
        asm volatile("cp.async.commit_group;");
    }
    float sc = scalaradd ? scalaradd[0] : 0.f;
    #pragma unroll
    for (int mi = 0; mi < 4; mi++) {
        int r0 = m0 + wm + mi * 16 + (lane >> 2);
        float ra0 = sc + (rowadd ? rowadd[(size_t)rowbat * bz + r0] : 0.f);
        float ra1 = sc + (rowadd ? rowadd[(size_t)rowbat * bz + r0 + 8] : 0.f);
        #pragma unroll
        for (int ni = 0; ni < 4; ni++) {
            int c0 = n0 + wn + ni * 8 + (lane & 3) * 2;
            float cb0 = coladd ? coladd[(size_t)colbat * bz + c0] : 0.f;
            float cb1 = coladd ? coladd[(size_t)colbat * bz + c0 + 1] : 0.f;
            float v00 = acc[mi][ni][0] + ra0 + cb0, v01 = acc[mi][ni][1] + ra0 + cb1;
            float v10 = acc[mi][ni][2] + ra1 + cb0, v11 = acc[mi][ni][3] + ra1 + cb1;
            if (bf16out) {
                __nv_bfloat16* Cb = (__nv_bfloat16*)Cout + Cbat * bz;
                *(uint32_t*)(Cb + (size_t)r0 * ldc + c0) = pkbf(v00, v01);
                *(uint32_t*)(Cb + (size_t)(r0 + 8) * ldc + c0) = pkbf(v10, v11);
            } else {
                float* Cf = (float*)Cout + Cbat * bz;
                *(float2*)(Cf + (size_t)r0 * ldc + c0) = make_float2(v00, v01);
                *(float2*)(Cf + (size_t)(r0 + 8) * ldc + c0) = make_float2(v10, v11);
            }
        }
    }
}

// ---------- final ----------
__global__ void k_final(const float* __restrict__ mask_src, float* __restrict__ out,
                        const float* __restrict__ dots, int B, int T, int S, float invscale) {
    int bt = blockIdx.x;
    int b = bt / T, t = bt - b * T;
    extern __shared__ float sm[];
    float* sp = sm;
    float* sl = sm + S;
    __shared__ float sred[32];
    float c = g_steps[b] * (float)t;
    float lmax = -INFINITY, qmax = -INFINITY;
    for (int s = threadIdx.x; s < S; s += blockDim.x) {
        float msk = 1.0f - mask_src[(size_t)b * S + s];
        float d = (float)s - c;
        float lg = -(d * d) / 0.3f - INF_ * msk;
        sl[s] = lg;
        lmax = fmaxf(lmax, lg);
        float x = (dots[(size_t)bt * S + s] - msk * INF_) * invscale;
        sp[s] = x;
        qmax = fmaxf(qmax, x);
    }
    lmax = bmax(lmax, sred);
    qmax = bmax(qmax, sred);
    float lsum = 0.f, qsum = 0.f;
    for (int s = threadIdx.x; s < S; s += blockDim.x) {
        float el = __expf(sl[s] - lmax);
        sl[s] = el;
        lsum += el;
        float eq = __expf(sp[s] - qmax);
        sp[s] = eq;
        qsum += eq;
    }
    lsum = bsum(lsum, sred);
    qsum = bsum(qsum, sred);
    float linv = 1.0f / lsum, qinv = 1.0f / qsum;
    float g = g_gates[bt];
    for (int s = threadIdx.x; s < S; s += blockDim.x)
        out[(size_t)bt * S + s] = (1.0f - g) * (sp[s] * qinv) + g * (sl[s] * linv);
}

// ---------- launch ----------
extern "C" void kernel_launch(void* const* d_in, const int* in_sizes, int n_in,
                              void* d_out, int out_size) {
    const float* key      = (const float*)d_in[0];
    const float* mask_src = (const float*)d_in[1];
    const float* mask_trg = (const float*)d_in[2];
    const float* Wq       = (const float*)d_in[3];
    const float* bq       = (const float*)d_in[4];
    const float* Wk       = (const float*)d_in[5];
    const float* bk       = (const float*)d_in[6];
    const float* wg       = (const float*)d_in[7];
    const float* bg       = (const float*)d_in[8];
    float* out = (float*)d_out;

    int D  = in_sizes[4];
    int BT = in_sizes[2];
    int S  = out_size / BT;
    int B  = in_sizes[1] / S;
    int T  = BT / B;

    float *p_c3, *p_at, *p_bs, *p_dots;
    __nv_bfloat16 *p_keyB, *p_queryB, *p_qmB, *p_MtB, *p_WqTB, *p_WkTB;
    cudaGetSymbolAddress((void**)&p_c3,    g_c3);
    cudaGetSymbolAddress((void**)&p_at,    g_at);
    cudaGetSymbolAddress((void**)&p_bs,    g_bs);
    cudaGetSymbolAddress((void**)&p_dots,  g_dots);
    cudaGetSymbolAddress((void**)&p_keyB,  g_keyB);
    cudaGetSymbolAddress((void**)&p_queryB, g_queryB);
    cudaGetSymbolAddress((void**)&p_qmB,   g_qmB);
    cudaGetSymbolAddress((void**)&p_MtB,   g_MtB);
    cudaGetSymbolAddress((void**)&p_WqTB,  g_WqTB);
    cudaGetSymbolAddress((void**)&p_WkTB,  g_WkTB);

    cudaFuncSetAttribute(k_bfgemm, cudaFuncAttributeMaxDynamicSharedMemorySize, GEMM_SMEM);

    // 1
    k_steps<<<B, 256>>>(mask_src, mask_trg, B, S, T);
    // 2
    {
        dim3 tb(32, 8);
        dim3 g(D / 32, D / 32, 2);
        k_transp2<<<g, tb>>>(Wq, Wk, D);
    }
    // 3
    k_cvecR<<<D, 128>>>(bq, bk, D);
    // 4: MtB[n,k] = sum_d WkTB[n,d]*WqTB[k,d]
    {
        dim3 g(D / 128, D / 128, 1);
        k_bfgemm<<<g, 256, GEMM_SMEM>>>(p_WkTB, p_WqTB, p_MtB, D, D, D, D,
                                        0, 0, 0, 1, nullptr, 0, nullptr, 0, nullptr);
    }
    // 5
    {
        dim3 g((T + QT - 1) / QT, B);
        k_query<<<g, 256>>>(mask_src, key, wg, bg, B, T, S, D);
    }
    // 6 (ncu capture target): qmB[m,n] = sum_k queryB[m,k]*MtB[n,k]
    {
        dim3 g(D / 128, BT / 128, 1);
        k_bfgemm<<<g, 256, GEMM_SMEM>>>(p_queryB, p_MtB, p_qmB, D, D, D, D,
                                        0, 0, 0, 1, nullptr, 0, nullptr, 0, nullptr);
    }
    // 7
    k_bskey<<<B * S, 128>>>(key, D);
    // 8: dots = qmB @ keyB^T + at + bs + c3
    {
        dim3 g(S / 128, T / 128, B);
        k_bfgemm<<<g, 256, GEMM_SMEM>>>(p_qmB, p_keyB, p_dots, D, D, D, S,
                                        (long long)T * D, (long long)S * D, (long long)T * S, 0,
                                        p_at, T, p_bs, S, p_c3);
    }
    // 9
    k_final<<<B * T, 256, 2 * S * (int)sizeof(float)>>>(mask_src, out, p_dots, B, T, S,
                                                        1.0f / sqrtf((float)D));
}

// round 10
// speedup vs baseline: 1.1200x; 1.0563x over previous
#include <cuda_runtime.h>
#include <cuda_bf16.h>
#include <stdint.h>
#include <math.h>

#define INF_ 1e10f

__device__ float g_dots [8388608];
__device__ float g_Mt   [1048576];
__device__ float g_WqT  [1048576];
__device__ float g_WkT  [1048576];
__device__ float g_c1   [1024];
__device__ float g_c2   [1024];
__device__ float g_c3   [1];
__device__ float g_steps[64];
__device__ float g_at   [8192];
__device__ float g_bs   [8192];
__device__ float g_gates[8192];
__device__ __nv_bfloat16 g_keyB  [8388608];
__device__ __nv_bfloat16 g_queryB[8388608];
__device__ __nv_bfloat16 g_qmB   [8388608];
__device__ __nv_bfloat16 g_MtB   [1048576];
__device__ __nv_bfloat16 g_WqTB  [1048576];
__device__ __nv_bfloat16 g_WkTB  [1048576];

// ---------- helpers ----------
__device__ __forceinline__ uint32_t pkbf(float a, float b) {
    __nv_bfloat162 t = __halves2bfloat162(__float2bfloat16(a), __float2bfloat16(b));
    return *reinterpret_cast<uint32_t*>(&t);
}
__device__ __forceinline__ float wsum(float v) {
    #pragma unroll
    for (int o = 16; o; o >>= 1) v += __shfl_xor_sync(0xffffffffu, v, o);
    return v;
}
__device__ __forceinline__ float wmax(float v) {
    #pragma unroll
    for (int o = 16; o; o >>= 1) v = fmaxf(v, __shfl_xor_sync(0xffffffffu, v, o));
    return v;
}
__device__ float bsum(float v, float* sb) {
    int lane = threadIdx.x & 31, w = threadIdx.x >> 5, nw = (blockDim.x + 31) >> 5;
    v = wsum(v);
    if (lane == 0) sb[w] = v;
    __syncthreads();
    v = (threadIdx.x < nw) ? sb[threadIdx.x] : 0.f;
    if (w == 0) v = wsum(v);
    if (threadIdx.x == 0) sb[0] = v;
    __syncthreads();
    v = sb[0];
    __syncthreads();
    return v;
}
__device__ float bmax(float v, float* sb) {
    int lane = threadIdx.x & 31, w = threadIdx.x >> 5, nw = (blockDim.x + 31) >> 5;
    v = wmax(v);
    if (lane == 0) sb[w] = v;
    __syncthreads();
    v = (threadIdx.x < nw) ? sb[threadIdx.x] : -INFINITY;
    if (w == 0) v = wmax(v);
    if (threadIdx.x == 0) sb[0] = v;
    __syncthreads();
    v = sb[0];
    __syncthreads();
    return v;
}

// ---------- small kernels ----------
__global__ void k_zero(float* __restrict__ p, int n4) {
    int i = blockIdx.x * blockDim.x + threadIdx.x;
    if (i < n4) ((float4*)p)[i] = make_float4(0.f, 0.f, 0.f, 0.f);
}

__global__ void k_cvt(const float* __restrict__ in, __nv_bfloat16* __restrict__ o, int n4) {
    int i = blockIdx.x * blockDim.x + threadIdx.x;
    if (i >= n4) return;
    float4 v = ((const float4*)in)[i];
    uint2 p;
    p.x = pkbf(v.x, v.y);
    p.y = pkbf(v.z, v.w);
    *(uint2*)(o + (size_t)i * 4) = p;
}

__global__ void k_steps(const float* __restrict__ ms, const float* __restrict__ mt,
                        int B, int S, int T) {
    int b = blockIdx.x;
    __shared__ float sb[32];
    float s = 0.f;
    for (int i = threadIdx.x; i < S; i += blockDim.x) s += ms[(size_t)b * S + i];
    s = bsum(s, sb);
    float t = 0.f;
    for (int i = threadIdx.x; i < T; i += blockDim.x) t += mt[(size_t)b * T + i];
    t = bsum(t, sb);
    if (threadIdx.x == 0) g_steps[b] = s / t;
}

__global__ void k_transp2(const float* __restrict__ Wq, const float* __restrict__ Wk, int D) {
    __shared__ float t[32][33];
    const float* in = blockIdx.z ? Wk : Wq;
    float* outp = blockIdx.z ? g_WkT : g_WqT;
    __nv_bfloat16* outb = blockIdx.z ? g_WkTB : g_WqTB;
    int x0 = blockIdx.x * 32, y0 = blockIdx.y * 32;
    int tx = threadIdx.x, ty = threadIdx.y;
    #pragma unroll
    for (int j = 0; j < 32; j += 8)
        t[ty + j][tx] = in[(size_t)(y0 + ty + j) * D + x0 + tx];
    __syncthreads();
    #pragma unroll
    for (int j = 0; j < 32; j += 8) {
        float v = t[tx][ty + j];
        size_t idx = (size_t)(x0 + ty + j) * D + y0 + tx;
        outp[idx] = v;
        outb[idx] = __float2bfloat16(v);
    }
}

__global__ void k_cvecR(const float* __restrict__ bq, const float* __restrict__ bk, int D) {
    int e = blockIdx.x;
    __shared__ float sb[32];
    const float4* r1 = (const float4*)(g_WqT + (size_t)e * D);
    const float4* r2 = (const float4*)(g_WkT + (size_t)e * D);
    float s1 = 0.f, s2 = 0.f, s3 = 0.f;
    for (int i = threadIdx.x; i < D / 4; i += blockDim.x) {
        float4 a = r1[i], c = *(const float4*)(bk + i * 4);
        s1 += a.x * c.x + a.y * c.y + a.z * c.z + a.w * c.w;
        float4 b2 = r2[i], d2 = *(const float4*)(bq + i * 4);
        s2 += b2.x * d2.x + b2.y * d2.y + b2.z * d2.z + b2.w * d2.w;
        if (e == 0) s3 += d2.x * c.x + d2.y * c.y + d2.z * c.z + d2.w * c.w;
    }
    s1 = bsum(s1, sb);
    s2 = bsum(s2, sb);
    if (e == 0) {
        s3 = bsum(s3, sb);
        if (threadIdx.x == 0) g_c3[0] = s3;
    }
    if (threadIdx.x == 0) { g_c1[e] = s1; g_c2[e] = s2; }
}

__global__ void k_bskey(const float* __restrict__ key, int D) {
    int r = blockIdx.x;
    __shared__ float sb[32];
    float s = 0.f;
    const float4* kr = (const float4*)(key + (size_t)r * D);
    uint2* ob = (uint2*)(g_keyB + (size_t)r * D);
    for (int i = threadIdx.x; i < D / 4; i += blockDim.x) {
        float4 kv = kr[i], cv = *(const float4*)(g_c2 + i * 4);
        s += kv.x * cv.x + kv.y * cv.y + kv.z * cv.z + kv.w * cv.w;
        uint2 p;
        p.x = pkbf(kv.x, kv.y);
        p.y = pkbf(kv.z, kv.w);
        ob[i] = p;
    }
    s = bsum(s, sb);
    if (threadIdx.x == 0) g_bs[r] = s;
}

// ---------- windowed query = l_att @ key, fused gates/at ----------
#define QT 16
__global__ __launch_bounds__(256) void k_query(const float* __restrict__ mask_src,
                                               const float* __restrict__ key,
                                               const float* __restrict__ wg,
                                               const float* __restrict__ bg,
                                               int B, int T, int S, int D) {
    __shared__ float wk[QT][64];
    __shared__ float s_c[QT], s_m[QT], s_inv[QT];
    __shared__ int s_s0[QT], s_s1[QT], sh_lo, sh_hi;
    __shared__ float red1[QT], red2[QT];
    int b = blockIdx.y, t0 = blockIdx.x * QT, tid = threadIdx.x;
    int lane = tid & 31;
    float step = g_steps[b];
    if (tid < QT) {
        red1[tid] = 0.f; red2[tid] = 0.f;
        int t = t0 + tid;
        if (t < T) {
            float c = step * (float)t;
            int ci = (int)lrintf(c);
            ci = min(max(ci, 0), S - 1);
            int a0 = max(0, ci - 16), a1 = min(S - 1, ci + 16);
            float mx = -INFINITY;
            for (int s = a0; s <= a1; s++) {
                float d = (float)s - c;
                mx = fmaxf(mx, -(d * d) / 0.3f - INF_ * (1.0f - mask_src[(size_t)b * S + s]));
            }
            float sum = 0.f;
            for (int s = a0; s <= a1; s++) {
                float d = (float)s - c;
                sum += __expf(-(d * d) / 0.3f - INF_ * (1.0f - mask_src[(size_t)b * S + s]) - mx);
            }
            s_c[tid] = c; s_m[tid] = mx; s_inv[tid] = 1.0f / sum;
            s_s0[tid] = a0; s_s1[tid] = a1;
        } else {
            s_c[tid] = 0.f; s_m[tid] = 0.f; s_inv[tid] = 0.f;
            s_s0[tid] = 1; s_s1[tid] = 0;
        }
    }
    __syncthreads();
    if (tid == 0) {
        int lo = s_s0[0], hi = s_s1[0];
        for (int i = 1; i < QT; i++)
            if (s_s1[i] >= s_s0[i]) { lo = min(lo, s_s0[i]); hi = max(hi, s_s1[i]); }
        sh_lo = lo; sh_hi = hi;
    }
    __syncthreads();
    int lo = sh_lo, hi = sh_hi;
    float4 acc[QT];
    #pragma unroll
    for (int r = 0; r < QT; r++) acc[r] = make_float4(0.f, 0.f, 0.f, 0.f);
    for (int c0 = lo; c0 <= hi; c0 += 64) {
        int cnt = min(64, hi - c0 + 1);
        __syncthreads();
        for (int i = tid; i < QT * 64; i += 256) {
            int tr = i >> 6, j = i & 63, s = c0 + j;
            float w = 0.f;
            if (j < cnt && s >= s_s0[tr] && s <= s_s1[tr]) {
                float d = (float)s - s_c[tr];
                w = __expf(-(d * d) / 0.3f - INF_ * (1.0f - mask_src[(size_t)b * S + s]) - s_m[tr]) * s_inv[tr];
            }
            wk[tr][j] = w;
        }
        __syncthreads();
        for (int j = 0; j < cnt; j++) {
            float4 kv = *(const float4*)(key + ((size_t)b * S + c0 + j) * D + tid * 4);
            #pragma unroll
            for (int r = 0; r < QT; r++) {
                float w = wk[r][j];
                acc[r].x = fmaf(w, kv.x, acc[r].x);
                acc[r].y = fmaf(w, kv.y, acc[r].y);
                acc[r].z = fmaf(w, kv.z, acc[r].z);
                acc[r].w = fmaf(w, kv.w, acc[r].w);
            }
        }
        __syncthreads();
    }
    float4 wgv = *(const float4*)(wg + tid * 4);
    float4 c1v = *(const float4*)(g_c1 + tid * 4);
    #pragma unroll
    for (int r = 0; r < QT; r++) {
        int t = t0 + r;
        if (t < T) {
            size_t base = ((size_t)b * T + t) * D + tid * 4;
            uint2 p;
            p.x = pkbf(acc[r].x, acc[r].y);
            p.y = pkbf(acc[r].z, acc[r].w);
            *(uint2*)(g_queryB + base) = p;
        }
        float p1 = acc[r].x * wgv.x + acc[r].y * wgv.y + acc[r].z * wgv.z + acc[r].w * wgv.w;
        float p2 = acc[r].x * c1v.x + acc[r].y * c1v.y + acc[r].z * c1v.z + acc[r].w * c1v.w;
        p1 = wsum(p1);
        p2 = wsum(p2);
        if (lane == 0) { atomicAdd(&red1[r], p1); atomicAdd(&red2[r], p2); }
    }
    __syncthreads();
    if (tid < QT) {
        int t = t0 + tid;
        if (t < T) {
            g_gates[(size_t)b * T + t] = 1.0f / (1.0f + __expf(-(red1[tid] + bg[0])));
            g_at[(size_t)b * T + t] = red2[tid];
        }
    }
}

// ---------- mma wrappers ----------
__device__ __forceinline__ void mma_bf16(float* c, const uint32_t* a, const uint32_t* b) {
    asm volatile("mma.sync.aligned.m16n8k16.row.col.f32.bf16.bf16.f32 "
                 "{%0,%1,%2,%3},{%4,%5,%6,%7},{%8,%9},{%0,%1,%2,%3};"
                 : "+f"(c[0]), "+f"(c[1]), "+f"(c[2]), "+f"(c[3])
                 : "r"(a[0]), "r"(a[1]), "r"(a[2]), "r"(a[3]), "r"(b[0]), "r"(b[1]));
}
__device__ __forceinline__ void cpa16(uint32_t saddr, const void* g) {
    asm volatile("cp.async.cg.shared.global [%0], [%1], 16;" :: "r"(saddr), "l"(g));
}
__device__ __forceinline__ void ldsm4(uint32_t* r, uint32_t addr) {
    asm volatile("ldmatrix.sync.aligned.m8n8.x4.shared.b16 {%0,%1,%2,%3}, [%4];"
                 : "=r"(r[0]), "=r"(r[1]), "=r"(r[2]), "=r"(r[3]) : "r"(addr));
}

// ---------- bf16 NT GEMM (ldmatrix, 4-stage, 1 sync/tile, loads-before-compute) ----------
// outmode: 0 = fp32 store, 1 = bf16 store, 2 = fp32 atomicAdd (split-K)
#define BQ 40
#define STG 4
#define SPITCH (128 * BQ)
#define GEMM_SMEM (STG * SPITCH * 2 * 2)
__global__ __launch_bounds__(256, 2) void k_bfgemm(
    const __nv_bfloat16* __restrict__ A, const __nv_bfloat16* __restrict__ B, void* __restrict__ Cout,
    int K, int lda, int ldb, int ldc,
    long long Abat, long long Bbat, long long Cbat, int outmode,
    const float* __restrict__ rowadd, int rowbat,
    const float* __restrict__ coladd, int colbat,
    const float* __restrict__ scalaradd)
{
    extern __shared__ __align__(16) __nv_bfloat16 dsm[];
    __nv_bfloat16* Asb = dsm;
    __nv_bfloat16* Bsb = dsm + STG * SPITCH;
    int tid = threadIdx.x, lane = tid & 31, wid = tid >> 5;
    int bz = blockIdx.z;
    A += Abat * bz; B += Bbat * bz;
    int m0 = blockIdx.y * 128, n0 = blockIdx.x * 128;
    int wm = (wid & 1) * 64, wn = (wid >> 1) * 32;
    float acc[4][4][4] = {};
    int lrow = tid >> 1, lcol = (tid & 1) * 16;
    const __nv_bfloat16* agp = A + (size_t)(m0 + lrow) * lda + lcol;
    const __nv_bfloat16* bgp = B + (size_t)(n0 + lrow) * ldb + lcol;
    int nk = K >> 5;
    int soff = lrow * BQ + lcol;
    #define LTB(kt, st) do { int _k = (kt) * 32; int _o = (st) * SPITCH + soff; \
        cpa16((uint32_t)__cvta_generic_to_shared(Asb + _o), agp + _k); \
        cpa16((uint32_t)__cvta_generic_to_shared(Asb + _o + 8), agp + _k + 8); \
        cpa16((uint32_t)__cvta_generic_to_shared(Bsb + _o), bgp + _k); \
        cpa16((uint32_t)__cvta_generic_to_shared(Bsb + _o + 8), bgp + _k + 8); \
    } while (0)

    #pragma unroll
    for (int i = 0; i < STG - 1; i++) {
        if (i < nk) LTB(i, i);
        asm volatile("cp.async.commit_group;");
    }
    int arow = (lane & 15), aoffb = (lane >> 4) * 8;
    int gq = lane >> 3;
    int brow = (gq >> 1) * 8 + (lane & 7), boffb = (gq & 1) * 8;
    for (int kt = 0; kt < nk; kt++) {
        int st = kt & (STG - 1);
        asm volatile("cp.async.wait_group %0;" :: "n"(STG - 2));
        __syncthreads();
        // issue next-stage loads before compute; write target was last read
        // at iteration kt-1 (before the sync above), so this is safe.
        if (kt + STG - 1 < nk) LTB(kt + STG - 1, (kt + STG - 1) & (STG - 1));
        asm volatile("cp.async.commit_group;");
        const __nv_bfloat16* Ast = Asb + st * SPITCH;
        const __nv_bfloat16* Bst = Bsb + st * SPITCH;
        #pragma unroll
        for (int kk = 0; kk < 32; kk += 16) {
            uint32_t ar[4][4], br[4][2];
            #pragma unroll
            for (int mi = 0; mi < 4; mi++)
                ldsm4(ar[mi], (uint32_t)__cvta_generic_to_shared(
                    Ast + (wm + mi * 16 + arow) * BQ + kk + aoffb));
            #pragma unroll
            for (int nj = 0; nj < 2; nj++) {
                uint32_t t4[4];
                ldsm4(t4, (uint32_t)__cvta_generic_to_shared(
                    Bst + (wn + nj * 16 + brow) * BQ + kk + boffb));
                br[nj * 2][0] = t4[0];
                br[nj * 2][1] = t4[1];
                br[nj * 2 + 1][0] = t4[2];
                br[nj * 2 + 1][1] = t4[3];
            }
            #pragma unroll
            for (int mi = 0; mi < 4; mi++)
                #pragma unroll
                for (int ni = 0; ni < 4; ni++)
                    mma_bf16(acc[mi][ni], ar[mi], br[ni]);
        }
    }
    float sc = scalaradd ? scalaradd[0] : 0.f;
    #pragma unroll
    for (int mi = 0; mi < 4; mi++) {
        int r0 = m0 + wm + mi * 16 + (lane >> 2);
        float ra0 = sc + (rowadd ? rowadd[(size_t)rowbat * bz + r0] : 0.f);
        float ra1 = sc + (rowadd ? rowadd[(size_t)rowbat * bz + r0 + 8] : 0.f);
        #pragma unroll
        for (int ni = 0; ni < 4; ni++) {
            int c0 = n0 + wn + ni * 8 + (lane & 3) * 2;
            float cb0 = coladd ? coladd[(size_t)colbat * bz + c0] : 0.f;
            float cb1 = coladd ? coladd[(size_t)colbat * bz + c0 + 1] : 0.f;
            float v00 = acc[mi][ni][0] + ra0 + cb0, v01 = acc[mi][ni][1] + ra0 + cb1;
            float v10 = acc[mi][ni][2] + ra1 + cb0, v11 = acc[mi][ni][3] + ra1 + cb1;
            if (outmode == 1) {
                __nv_bfloat16* Cb = (__nv_bfloat16*)Cout + Cbat * bz;
                *(uint32_t*)(Cb + (size_t)r0 * ldc + c0) = pkbf(v00, v01);
                *(uint32_t*)(Cb + (size_t)(r0 + 8) * ldc + c0) = pkbf(v10, v11);
            } else if (outmode == 0) {
                float* Cf = (float*)Cout + Cbat * bz;
                *(float2*)(Cf + (size_t)r0 * ldc + c0) = make_float2(v00, v01);
                *(float2*)(Cf + (size_t)(r0 + 8) * ldc + c0) = make_float2(v10, v11);
            } else {
                float* Cf = (float*)Cout;
                atomicAdd(Cf + (size_t)r0 * ldc + c0, v00);
                atomicAdd(Cf + (size_t)r0 * ldc + c0 + 1, v01);
                atomicAdd(Cf + (size_t)(r0 + 8) * ldc + c0, v10);
                atomicAdd(Cf + (size_t)(r0 + 8) * ldc + c0 + 1, v11);
            }
        }
    }
}

// ---------- final ----------
__global__ void k_final(const float* __restrict__ mask_src, float* __restrict__ out,
                        const float* __restrict__ dots, int B, int T, int S, float invscale) {
    int bt = blockIdx.x;
    int b = bt / T, t = bt - b * T;
    extern __shared__ float sm[];
    float* sp = sm;
    float* sl = sm + S;
    __shared__ float sred[32];
    float c = g_steps[b] * (float)t;
    float lmax = -INFINITY, qmax = -INFINITY;
    for (int s = threadIdx.x; s < S; s += blockDim.x) {
        float msk = 1.0f - mask_src[(size_t)b * S + s];
        float d = (float)s - c;
        float lg = -(d * d) / 0.3f - INF_ * msk;
        sl[s] = lg;
        lmax = fmaxf(lmax, lg);
        float x = (dots[(size_t)bt * S + s] - msk * INF_) * invscale;
        sp[s] = x;
        qmax = fmaxf(qmax, x);
    }
    lmax = bmax(lmax, sred);
    qmax = bmax(qmax, sred);
    float lsum = 0.f, qsum = 0.f;
    for (int s = threadIdx.x; s < S; s += blockDim.x) {
        float el = __expf(sl[s] - lmax);
        sl[s] = el;
        lsum += el;
        float eq = __expf(sp[s] - qmax);
        sp[s] = eq;
        qsum += eq;
    }
    lsum = bsum(lsum, sred);
    qsum = bsum(qsum, sred);
    float linv = 1.0f / lsum, qinv = 1.0f / qsum;
    float g = g_gates[bt];
    for (int s = threadIdx.x; s < S; s += blockDim.x)
        out[(size_t)bt * S + s] = (1.0f - g) * (sp[s] * qinv) + g * (sl[s] * linv);
}

// ---------- launch ----------
extern "C" void kernel_launch(void* const* d_in, const int* in_sizes, int n_in,
                              void* d_out, int out_size) {
    const float* key      = (const float*)d_in[0];
    const float* mask_src = (const float*)d_in[1];
    const float* mask_trg = (const float*)d_in[2];
    const float* Wq       = (const float*)d_in[3];
    const float* bq       = (const float*)d_in[4];
    const float* Wk       = (const float*)d_in[5];
    const float* bk       = (const float*)d_in[6];
    const float* wg       = (const float*)d_in[7];
    const float* bg       = (const float*)d_in[8];
    float* out = (float*)d_out;

    int D  = in_sizes[4];
    int BT = in_sizes[2];
    int S  = out_size / BT;
    int B  = in_sizes[1] / S;
    int T  = BT / B;

    float *p_Mt, *p_c3, *p_at, *p_bs, *p_dots;
    __nv_bfloat16 *p_keyB, *p_queryB, *p_qmB, *p_MtB, *p_WqTB, *p_WkTB;
    cudaGetSymbolAddress((void**)&p_Mt,    g_Mt);
    cudaGetSymbolAddress((void**)&p_c3,    g_c3);
    cudaGetSymbolAddress((void**)&p_at,    g_at);
    cudaGetSymbolAddress((void**)&p_bs,    g_bs);
    cudaGetSymbolAddress((void**)&p_dots,  g_dots);
    cudaGetSymbolAddress((void**)&p_keyB,  g_keyB);
    cudaGetSymbolAddress((void**)&p_queryB, g_queryB);
    cudaGetSymbolAddress((void**)&p_qmB,   g_qmB);
    cudaGetSymbolAddress((void**)&p_MtB,   g_MtB);
    cudaGetSymbolAddress((void**)&p_WqTB,  g_WqTB);
    cudaGetSymbolAddress((void**)&p_WkTB,  g_WkTB);

    cudaFuncSetAttribute(k_bfgemm, cudaFuncAttributeMaxDynamicSharedMemorySize, GEMM_SMEM);

    k_steps<<<B, 256>>>(mask_src, mask_trg, B, S, T);
    {
        dim3 tb(32, 8);
        dim3 g(D / 32, D / 32, 2);
        k_transp2<<<g, tb>>>(Wq, Wk, D);
    }
    k_cvecR<<<D, 128>>>(bq, bk, D);
    k_zero<<<(D * D / 4 + 255) / 256, 256>>>(p_Mt, D * D / 4);
    // Mt[n,k] = sum_d WkTB[n,d]*WqTB[k,d]  (split-K x4, fp32 atomic accumulate)
    {
        dim3 g(D / 128, D / 128, 4);
        k_bfgemm<<<g, 256, GEMM_SMEM>>>(p_WkTB, p_WqTB, p_Mt, D / 4, D, D, D,
                                        D / 4, D / 4, 0, 2, nullptr, 0, nullptr, 0, nullptr);
    }
    k_cvt<<<(D * D / 4 + 255) / 256, 256>>>(p_Mt, p_MtB, D * D / 4);
    {
        dim3 g((T + QT - 1) / QT, B);
        k_query<<<g, 256>>>(mask_src, key, wg, bg, B, T, S, D);
    }
    // qmB[m,n] = sum_k queryB[m,k]*MtB[n,k]
    {
        dim3 g(D / 128, BT / 128, 1);
        k_bfgemm<<<g, 256, GEMM_SMEM>>>(p_queryB, p_MtB, p_qmB, D, D, D, D,
                                        0, 0, 0, 1, nullptr, 0, nullptr, 0, nullptr);
    }
    k_bskey<<<B * S, 128>>>(key, D);
    // dots = qmB @ keyB^T + at + bs + c3
    {
        dim3 g(S / 128, T / 128, B);
        k_bfgemm<<<g, 256, GEMM_SMEM>>>(p_qmB, p_keyB, p_dots, D, D, D, S,
                                        (long long)T * D, (long long)S * D, (long long)T * S, 0,
                                        p_at, T, p_bs, S, p_c3);
    }
    k_final<<<B * T, 256, 2 * S * (int)sizeof(float)>>>(mask_src, out, p_dots, B, T, S,
                                                        1.0f / sqrtf((float)D));
}